// round 17
// baseline (speedup 1.0000x reference)
#include <cuda_runtime.h>

#define N_SAMPLES 65536
#define EMB       1536
#define HALF      768
#define BINS      257
#define PLANE     (BINS * BINS)
#define ROW_F4    (EMB / 4)       // 384
#define HALF_F4   (HALF / 4)      // 192

#define PCHUNKS     9
#define BUILD_CTAS  576
#define BUILD_WARPS (BUILD_CTAS * 8)

// Factored table T[p][e] = pe_value(e,p) + lc[e]  (1.58 MB, L2-resident)
__device__ __align__(128) float g_table[BINS * EMB];
// Counting-sort state (counters zeroed by builder each launch)
__device__ int g_cntW[BINS], g_cntH[BINS];
__device__ int g_offW[BINS], g_offH[BINS];          // scan results, then cursors
__device__ unsigned g_ordW[N_SAMPLES], g_ordH[N_SAMPLES];  // row | (bin<<16)

// ---------------------------------------------------------------------------
// Kernel A (R11-proven): balanced single-wave builder + counter zeroing.
// ---------------------------------------------------------------------------
__global__ void __launch_bounds__(256)
build_table_kernel(const float* __restrict__ pe, const float* __restrict__ lc) {
    if (blockIdx.x == 0 && threadIdx.x < BINS) {
        g_cntW[threadIdx.x] = 0;
        g_cntH[threadIdx.x] = 0;
    }
    const int w    = blockIdx.x * 8 + (threadIdx.x >> 5);
    const int lane = threadIdx.x & 31;
    int ev[3], pv[3]; float val[3], bias[3];
    #pragma unroll
    for (int t = 0; t < 3; t++) {
        const int task = w + t * BUILD_WARPS;
        const int e = task / PCHUNKS;
        const int k = task - e * PCHUNKS;
        const int p = k * 32 + lane;
        ev[t] = e; pv[t] = p;
        if (p < BINS) {
            const size_t off = (e < HALF) ? (size_t)p : (size_t)p * BINS;
            val[t]  = __ldg(&pe[(size_t)e * PLANE + off]);
            bias[t] = __ldg(&lc[e]);
        }
    }
    #pragma unroll
    for (int t = 0; t < 3; t++)
        if (pv[t] < BINS) g_table[(size_t)pv[t] * EMB + ev[t]] = val[t] + bias[t];
}

// Exact digitize (rel_err == 0.0 validated R1-R15). Result in [1, 256].
__device__ __forceinline__ int digitize256(float x) {
    float xc = fminf(fmaxf(x, -5.0f), 5.0f - 1e-6f);
    int k = (int)floorf((xc + 5.0f) * 25.6f);
    k = max(0, min(k, 255));
    while (k < 255 && fmaf((float)(k + 1), 0.0390625f, -5.0f) <= xc) k++;
    while (k > 0   && fmaf((float)k,       0.0390625f, -5.0f) >  xc) k--;
    return k + 1;
}

// ---------------------------------------------------------------------------
// Kernel B: histogram both sides.
// ---------------------------------------------------------------------------
__global__ void __launch_bounds__(256)
count_kernel(const float* __restrict__ x1, const float* __restrict__ x2) {
    const int i = blockIdx.x * 256 + threadIdx.x;
    atomicAdd(&g_cntW[digitize256(__ldg(&x2[i]))], 1);
    atomicAdd(&g_cntH[digitize256(__ldg(&x1[i]))], 1);
}

// ---------------------------------------------------------------------------
// Kernel C: exclusive scan of both 257-bin histograms.
// FIX vs R16: 544 threads (>= 2*257 = 514 lanes); 512 left sH[255..256]
// unscanned -> garbage offsets -> 5.8e-2 rel_err.
// ---------------------------------------------------------------------------
__global__ void __launch_bounds__(544)
scan_kernel() {
    __shared__ int sW[BINS], sH[BINS];
    const int t = threadIdx.x;
    if (t < BINS) sW[t] = g_cntW[t];
    else if (t < 2 * BINS) sH[t - BINS] = g_cntH[t - BINS];
    __syncthreads();
    for (int off = 1; off < BINS; off <<= 1) {
        int v = 0;
        if (t < BINS)            { if (t >= off) v = sW[t - off]; }
        else if (t < 2 * BINS)   { int i = t - BINS; if (i >= off) v = sH[i - off]; }
        __syncthreads();
        if (t < BINS) sW[t] += v;
        else if (t < 2 * BINS) sH[t - BINS] += v;
        __syncthreads();
    }
    if (t < BINS) g_offW[t] = sW[t] - g_cntW[t];
    else if (t < 2 * BINS) g_offH[t - BINS] = sH[t - BINS] - g_cntH[t - BINS];
}

// ---------------------------------------------------------------------------
// Kernel D: scatter rows into bin-sorted order (cursors = scan results).
// Order within a bin is nondeterministic; the final output is order-invariant.
// ---------------------------------------------------------------------------
__global__ void __launch_bounds__(256)
scatter_kernel(const float* __restrict__ x1, const float* __restrict__ x2) {
    const int i = blockIdx.x * 256 + threadIdx.x;
    const int i2 = digitize256(__ldg(&x2[i]));
    g_ordW[atomicAdd(&g_offW[i2], 1)] = (unsigned)i | ((unsigned)i2 << 16);
    const int i1 = digitize256(__ldg(&x1[i]));
    g_ordH[atomicAdd(&g_offH[i1], 1)] = (unsigned)i | ((unsigned)i1 << 16);
}

// ---------------------------------------------------------------------------
// Kernel E: sorted copy. bid < 2048 -> W pass (left 3KB halves, ordW order);
// bid >= 2048 -> H pass (right halves, ordH order). Each warp takes 4
// CONSECUTIVE sorted entries -> same/adjacent bin -> table reads are L1
// broadcast hits; L2 read traffic collapses. Writes: full 3KB contiguous
// segment per row (__stcs streaming).
// ---------------------------------------------------------------------------
__global__ void __launch_bounds__(256)
sorted_copy_kernel(float4* __restrict__ out) {
    const float4* __restrict__ tab = reinterpret_cast<const float4*>(g_table);
    const int warp = threadIdx.x >> 5;
    const int lane = threadIdx.x & 31;
    const bool hpass = (blockIdx.x >= 2048);
    const int gw = (hpass ? blockIdx.x - 2048 : blockIdx.x) * 8 + warp; // 0..16383
    const unsigned* __restrict__ ord = hpass ? g_ordH : g_ordW;
    const int tabOff = hpass ? HALF_F4 : 0;

    #pragma unroll
    for (int j = 0; j < 4; j++) {
        const unsigned ent = __ldg(&ord[gw * 4 + j]);
        const unsigned row = ent & 0xFFFFu;
        const unsigned bin = ent >> 16;
        const float4* __restrict__ src = tab + (size_t)bin * ROW_F4 + tabOff;
        float4* __restrict__ dst = out + (size_t)row * ROW_F4 + tabOff;
        #pragma unroll
        for (int k = 0; k < 6; k++) {
            const int e4 = k * 32 + lane;          // 0..191 within the half
            __stcs(&dst[e4], __ldg(&src[e4]));
        }
    }
}

extern "C" void kernel_launch(void* const* d_in, const int* in_sizes, int n_in,
                              void* d_out, int out_size) {
    const float* x1 = (const float*)d_in[0];
    const float* x2 = (const float*)d_in[1];
    const float* pe = (const float*)d_in[2];
    const float* lc = (const float*)d_in[3];
    float4* out = (float4*)d_out;

    build_table_kernel<<<BUILD_CTAS, 256>>>(pe, lc);
    count_kernel<<<N_SAMPLES / 256, 256>>>(x1, x2);
    scan_kernel<<<1, 544>>>();
    scatter_kernel<<<N_SAMPLES / 256, 256>>>(x1, x2);
    sorted_copy_kernel<<<4096, 256>>>(out);
}